// round 5
// baseline (speedup 1.0000x reference)
#include <cuda_runtime.h>
#include <cstdint>

#define Bc 1024
#define Sc 1024
#define Fc 36
#define Hc 20

typedef unsigned long long u64;

// ---------- packed f32x2 + fast-math helpers ----------
__device__ __forceinline__ u64 pk2(float lo, float hi) {
    u64 r; asm("mov.b64 %0, {%1, %2};" : "=l"(r) : "f"(lo), "f"(hi)); return r;
}
__device__ __forceinline__ void upk2(u64 v, float& lo, float& hi) {
    asm("mov.b64 {%0, %1}, %2;" : "=f"(lo), "=f"(hi) : "l"(v));
}
__device__ __forceinline__ u64 fma2(u64 a, u64 b, u64 c) {
    u64 d; asm("fma.rn.f32x2 %0, %1, %2, %3;" : "=l"(d) : "l"(a), "l"(b), "l"(c)); return d;
}
__device__ __forceinline__ u64 add2(u64 a, u64 b) {
    u64 d; asm("add.rn.f32x2 %0, %1, %2;" : "=l"(d) : "l"(a), "l"(b)); return d;
}
__device__ __forceinline__ float ex2a(float x) { float r; asm("ex2.approx.f32 %0, %1;" : "=f"(r) : "f"(x)); return r; }
__device__ __forceinline__ float rcpa(float x) { float r; asm("rcp.approx.f32 %0, %1;" : "=f"(r) : "f"(x)); return r; }
__device__ __forceinline__ float sigm(float x) { return rcpa(1.0f + ex2a(-1.4426950408889634f * x)); }
__device__ __forceinline__ float tanh_(float x) {
    return fmaf(2.0f, rcpa(1.0f + ex2a(-2.8853900817779268f * x)), -1.0f);
}

// ---------- kernel 1: embedding concat -> origin (detection folded in) ----------
__global__ void embed_kernel(const float* __restrict__ x, const void* __restrict__ ohraw,
                             const float* __restrict__ e0, const float* __restrict__ e1,
                             const float* __restrict__ e2, const float* __restrict__ e3,
                             float* __restrict__ org)
{
    // warp-uniform dtype probe: int64 little-endian small values => odd words zero
    int lane = threadIdx.x & 31;
    int probe = ((const int*)ohraw)[2 * lane + 1];
    unsigned m = __ballot_sync(0xFFFFFFFFu, probe != 0);
    bool is64 = (m == 0);

    int idx = blockIdx.x * blockDim.x + threadIdx.x;
    if (idx >= Bc * Sc) return;
    const float4* xr = reinterpret_cast<const float4*>(x + (size_t)idx * 12);
    float4 v0 = xr[0], v1 = xr[1], v2 = xr[2];

    long long i0, i1, i2, i3;
    if (is64) {
        const longlong2* op = reinterpret_cast<const longlong2*>((const long long*)ohraw + (size_t)idx * 4);
        longlong2 a = op[0], b = op[1];
        i0 = a.x; i1 = a.y; i2 = b.x; i3 = b.y;
    } else {
        int4 a = *reinterpret_cast<const int4*>((const int*)ohraw + (size_t)idx * 4);
        i0 = a.x; i1 = a.y; i2 = a.z; i3 = a.w;
    }
    i0 = i0 < 0 ? 0 : (i0 > 9  ? 9  : i0);
    i1 = i1 < 0 ? 0 : (i1 > 19 ? 19 : i1);
    i2 = i2 < 0 ? 0 : (i2 > 49 ? 49 : i2);
    i3 = i3 < 0 ? 0 : (i3 > 99 ? 99 : i3);

    float4* out = reinterpret_cast<float4*>(org + (size_t)idx * 36);
    out[0] = v0; out[1] = v1; out[2] = v2;
    out[3] = *reinterpret_cast<const float4*>(e0 + i0 * 4);
    out[4] = *reinterpret_cast<const float4*>(e1 + i1 * 4);
    const float4* p2 = reinterpret_cast<const float4*>(e2 + i2 * 8);
    out[5] = p2[0]; out[6] = p2[1];
    const float4* p3 = reinterpret_cast<const float4*>(e3 + i3 * 8);
    out[7] = p3[0]; out[8] = p3[1];
}

// ---------- packed dots: weights in regs, x/h broadcast from shared ----------
__device__ __forceinline__ u64 dot36(const u64* __restrict__ xsh, const u64* w, u64 acc0) {
    const ulonglong2* xp = reinterpret_cast<const ulonglong2*>(xsh);
    u64 a0 = acc0, a1 = 0ULL, a2 = 0ULL, a3 = 0ULL;
#pragma unroll
    for (int k = 0; k < 18; k++) {
        ulonglong2 v = xp[k];
        if ((k & 1) == 0) { a0 = fma2(v.x, w[2*k], a0); a1 = fma2(v.y, w[2*k+1], a1); }
        else              { a2 = fma2(v.x, w[2*k], a2); a3 = fma2(v.y, w[2*k+1], a3); }
    }
    return add2(add2(a0, a2), add2(a1, a3));
}
__device__ __forceinline__ u64 dot20(const u64* __restrict__ hsh, const u64* w, u64 acc0) {
    const ulonglong2* hp = reinterpret_cast<const ulonglong2*>(hsh);
    u64 a0 = acc0, a1 = 0ULL, a2 = 0ULL, a3 = 0ULL;
#pragma unroll
    for (int k = 0; k < 10; k++) {
        ulonglong2 v = hp[k];
        if ((k & 1) == 0) { a0 = fma2(v.x, w[2*k], a0); a1 = fma2(v.y, w[2*k+1], a1); }
        else              { a2 = fma2(v.x, w[2*k], a2); a3 = fma2(v.y, w[2*k+1], a3); }
    }
    return add2(add2(a0, a2), add2(a1, a3));
}

// ---------- kernel 2: persistent GRU, 64 threads (2 warps) per block ----------
// Lane l (<60): full gate row l (56 dup-packed u64 = 112 regs).
// h phase: lanes 0..19 (warp 0). FC: lanes 0..17, 2 rows each (warp 0) — only a
// __syncwarp between h and FC. Prefetch: warp-1 lanes 32..40 (idle during h).
__global__ void __launch_bounds__(64) gru_kernel(
    const float* __restrict__ org,
    const float* __restrict__ Wih1, const float* __restrict__ Whh1,
    const float* __restrict__ bih1, const float* __restrict__ bhh1,
    const float* __restrict__ Wih2, const float* __restrict__ Whh2,
    const float* __restrict__ bih2, const float* __restrict__ bhh2,
    const float* __restrict__ Wfc,  const float* __restrict__ bfc,
    float* __restrict__ xs)
{
    const int l = threadIdx.x;
    const int b0 = blockIdx.x * 2;
    const size_t base0 = (size_t)b0 * Sc * Fc;
    const size_t base1 = base0 + (size_t)Sc * Fc;

    __shared__ __align__(16) u64 xring[4][Fc];
    __shared__ __align__(16) u64 hbuf[Hc];
    __shared__ __align__(16) u64 g[40];       // r,z gates combined (gi+gh+biases)
    __shared__ __align__(16) u64 gan[Hc];     // n gate: gi+bih
    __shared__ __align__(16) u64 gbn[Hc];     // n gate: gh+bhh
    __shared__ __align__(16) u64 xdec[Fc];
    __shared__ __align__(16) u64 wfcT[Hc][Fc];  // transposed FC weights, dup-packed

    const bool gate = (l < 60);
    const bool hl   = (l < Hc);
    const bool fcl  = (l < 18);
    const int  pi   = l - 32;                  // prefetch chunk 0..8
    const bool pfl  = (pi >= 0) && (pi < 9);

    u64 wx[Fc], wh[Hc];
    u64 bsum = 0ULL, ban = 0ULL, bbn = 0ULL;   // combined bias (r,z) / split (n)
    u64 bfcA = 0ULL, bfcB = 0ULL;

    // encoder gate weights -> regs
    if (gate) {
#pragma unroll
        for (int f = 0; f < Fc; f++) { float w = Wih1[l * Fc + f]; wx[f] = pk2(w, w); }
#pragma unroll
        for (int k = 0; k < Hc; k++) { float w = Whh1[l * Hc + k]; wh[k] = pk2(w, w); }
        if (l < 40) { float s = bih1[l] + bhh1[l]; bsum = pk2(s, s); }
        else { float t1 = bih1[l]; ban = pk2(t1, t1); float t2 = bhh1[l]; bbn = pk2(t2, t2); }
    }
    // FC weights transposed into shared
    for (int idx = l; idx < Hc * Fc; idx += 64) {
        int k = idx / Fc, r = idx % Fc;
        float w = Wfc[r * Hc + k];
        wfcT[k][r] = pk2(w, w);
    }
    if (fcl) {
        float tA = bfc[2 * l];     bfcA = pk2(tA, tA);
        float tB = bfc[2 * l + 1]; bfcB = pk2(tB, tB);
    }
    if (hl) hbuf[l] = 0ULL;

    // prefetch prologue: slots 0,1 filled; qA=x(2), qB=x(3)
    float4 qA0, qA1, qB0, qB1;
    qA0 = qA1 = qB0 = qB1 = make_float4(0.f, 0.f, 0.f, 0.f);
    if (pfl) {
#pragma unroll
        for (int s = 0; s < 2; s++) {
            float4 a = *reinterpret_cast<const float4*>(org + base0 + s * Fc + pi * 4);
            float4 b = *reinterpret_cast<const float4*>(org + base1 + s * Fc + pi * 4);
            ulonglong2* dst = reinterpret_cast<ulonglong2*>(&xring[s][pi * 4]);
            dst[0] = make_ulonglong2(pk2(a.x, b.x), pk2(a.y, b.y));
            dst[1] = make_ulonglong2(pk2(a.z, b.z), pk2(a.w, b.w));
        }
        qA0 = *reinterpret_cast<const float4*>(org + base0 + 2 * Fc + pi * 4);
        qA1 = *reinterpret_cast<const float4*>(org + base1 + 2 * Fc + pi * 4);
        qB0 = *reinterpret_cast<const float4*>(org + base0 + 3 * Fc + pi * 4);
        qB1 = *reinterpret_cast<const float4*>(org + base1 + 3 * Fc + pi * 4);
    }
    __syncthreads();

    // ================= encoder: S steps, 2 bars/step =================
    for (int t = 0; t < Sc; t++) {
        float4 n0 = make_float4(0.f,0.f,0.f,0.f), n1 = n0;
        if (pfl) {
            if (t + 4 < Sc) {   // LDG issued 2 steps before its STS
                n0 = *reinterpret_cast<const float4*>(org + base0 + (size_t)(t + 4) * Fc + pi * 4);
                n1 = *reinterpret_cast<const float4*>(org + base1 + (size_t)(t + 4) * Fc + pi * 4);
            }
            int s = (t + 2) & 3;     // store x(t+2), consumed 2 steps later
            ulonglong2* dst = reinterpret_cast<ulonglong2*>(&xring[s][pi * 4]);
            dst[0] = make_ulonglong2(pk2(qA0.x, qA1.x), pk2(qA0.y, qA1.y));
            dst[1] = make_ulonglong2(pk2(qA0.z, qA1.z), pk2(qA0.w, qA1.w));
        }
        if (gate) {
            if (l < 40) {
                u64 aa = dot36(xring[t & 3], wx, bsum);
                u64 bb = dot20(hbuf, wh, 0ULL);
                g[l] = add2(aa, bb);
            } else {
                gan[l - 40] = dot36(xring[t & 3], wx, ban);
                gbn[l - 40] = dot20(hbuf, wh, bbn);
            }
        }
        qA0 = qB0; qA1 = qB1; qB0 = n0; qB1 = n1;
        __syncthreads();
        if (hl) {
            float rx, ry, zx, zy, ax, ay, bx, by, hx, hy;
            upk2(g[l], rx, ry); upk2(g[l + 20], zx, zy);
            upk2(gan[l], ax, ay); upk2(gbn[l], bx, by);
            upk2(hbuf[l], hx, hy);
            float r0 = sigm(rx), r1 = sigm(ry);
            float z0 = sigm(zx), z1 = sigm(zy);
            float nn0 = tanh_(fmaf(r0, bx, ax));
            float nn1 = tanh_(fmaf(r1, by, ay));
            hbuf[l] = pk2(fmaf(z0, hx - nn0, nn0), fmaf(z1, hy - nn1, nn1));
        }
        __syncthreads();
    }

    // ================= phase switch =================
    if (gate) {
#pragma unroll
        for (int f = 0; f < Fc; f++) { float w = Wih2[l * Fc + f]; wx[f] = pk2(w, w); }
#pragma unroll
        for (int k = 0; k < Hc; k++) { float w = Whh2[l * Hc + k]; wh[k] = pk2(w, w); }
        if (l < 40) { float s = bih2[l] + bhh2[l]; bsum = pk2(s, s); }
        else { float t1 = bih2[l]; ban = pk2(t1, t1); float t2 = bhh2[l]; bbn = pk2(t2, t2); }
    }
    if (hl) {
        float hx, hy; upk2(hbuf[l], hx, hy);
        hbuf[l] = pk2(tanh_(hx), tanh_(hy));
    }
    __syncthreads();

    // x0 = tanh(h @ Wfc.T + bfc) -> xs[:, S-1, :]
    if (fcl) {
        const ulonglong2* hp = reinterpret_cast<const ulonglong2*>(hbuf);
        u64 aA0 = bfcA, aA1 = 0ULL, aB0 = bfcB, aB1 = 0ULL;
#pragma unroll
        for (int k = 0; k < 10; k++) {
            ulonglong2 hv = hp[k];
            ulonglong2 w0 = *reinterpret_cast<const ulonglong2*>(&wfcT[2*k][2*l]);
            ulonglong2 w1 = *reinterpret_cast<const ulonglong2*>(&wfcT[2*k+1][2*l]);
            aA0 = fma2(hv.x, w0.x, aA0); aB0 = fma2(hv.x, w0.y, aB0);
            aA1 = fma2(hv.y, w1.x, aA1); aB1 = fma2(hv.y, w1.y, aB1);
        }
        u64 accA = add2(aA0, aA1), accB = add2(aB0, aB1);
        float a0, a1, c0, c1;
        upk2(accA, a0, a1); upk2(accB, c0, c1);
        a0 = tanh_(a0); a1 = tanh_(a1); c0 = tanh_(c0); c1 = tanh_(c1);
        *reinterpret_cast<ulonglong2*>(&xdec[2*l]) = make_ulonglong2(pk2(a0, a1), pk2(c0, c1));
        const size_t row = (size_t)(Sc - 1) * Fc;
        *reinterpret_cast<float2*>(xs + base0 + row + 2*l) = make_float2(a0, c0);
        *reinterpret_cast<float2*>(xs + base1 + row + 2*l) = make_float2(a1, c1);
    }
    __syncthreads();

    // ================= decoder: S-1 steps, 2 bars/step =================
    for (int k = 1; k < Sc; k++) {
        if (gate) {
            if (l < 40) {
                u64 aa = dot36(xdec, wx, bsum);
                u64 bb = dot20(hbuf, wh, 0ULL);
                g[l] = add2(aa, bb);
            } else {
                gan[l - 40] = dot36(xdec, wx, ban);
                gbn[l - 40] = dot20(hbuf, wh, bbn);
            }
        }
        __syncthreads();
        if (hl) {
            float rx, ry, zx, zy, ax, ay, bx, by, hx, hy;
            upk2(g[l], rx, ry); upk2(g[l + 20], zx, zy);
            upk2(gan[l], ax, ay); upk2(gbn[l], bx, by);
            upk2(hbuf[l], hx, hy);
            float r0 = sigm(rx), r1 = sigm(ry);
            float z0 = sigm(zx), z1 = sigm(zy);
            float nn0 = tanh_(fmaf(r0, bx, ax));
            float nn1 = tanh_(fmaf(r1, by, ay));
            float g0 = fmaf(z0, hx - nn0, nn0);
            float g1 = fmaf(z1, hy - nn1, nn1);
            hbuf[l] = pk2(tanh_(g0), tanh_(g1));   // decoder outer tanh
        }
        if (l < 32) __syncwarp();                  // h -> FC, warp 0 only
        if (fcl) {
            const ulonglong2* hp = reinterpret_cast<const ulonglong2*>(hbuf);
            u64 aA0 = bfcA, aA1 = 0ULL, aB0 = bfcB, aB1 = 0ULL;
#pragma unroll
            for (int kk = 0; kk < 10; kk++) {
                ulonglong2 hv = hp[kk];
                ulonglong2 w0 = *reinterpret_cast<const ulonglong2*>(&wfcT[2*kk][2*l]);
                ulonglong2 w1 = *reinterpret_cast<const ulonglong2*>(&wfcT[2*kk+1][2*l]);
                aA0 = fma2(hv.x, w0.x, aA0); aB0 = fma2(hv.x, w0.y, aB0);
                aA1 = fma2(hv.y, w1.x, aA1); aB1 = fma2(hv.y, w1.y, aB1);
            }
            u64 accA = add2(aA0, aA1), accB = add2(aB0, aB1);
            float a0, a1, c0, c1;
            upk2(accA, a0, a1); upk2(accB, c0, c1);
            a0 = tanh_(a0); a1 = tanh_(a1); c0 = tanh_(c0); c1 = tanh_(c1);
            *reinterpret_cast<ulonglong2*>(&xdec[2*l]) = make_ulonglong2(pk2(a0, a1), pk2(c0, c1));
            const size_t row = (size_t)(Sc - 1 - k) * Fc;
            *reinterpret_cast<float2*>(xs + base0 + row + 2*l) = make_float2(a0, c0);
            *reinterpret_cast<float2*>(xs + base1 + row + 2*l) = make_float2(a1, c1);
        }
        __syncthreads();
    }
}

// ---------- launcher ----------
extern "C" void kernel_launch(void* const* d_in, const int* in_sizes, int n_in,
                              void* d_out, int out_size)
{
    const float* x    = (const float*)d_in[0];
    const void*  oh   = d_in[1];
    const float* e0   = (const float*)d_in[2];
    const float* e1   = (const float*)d_in[3];
    const float* e2   = (const float*)d_in[4];
    const float* e3   = (const float*)d_in[5];
    const float* Wih1 = (const float*)d_in[6];
    const float* Whh1 = (const float*)d_in[7];
    const float* bih1 = (const float*)d_in[8];
    const float* bhh1 = (const float*)d_in[9];
    const float* Wih2 = (const float*)d_in[10];
    const float* Whh2 = (const float*)d_in[11];
    const float* bih2 = (const float*)d_in[12];
    const float* bhh2 = (const float*)d_in[13];
    const float* Wfc  = (const float*)d_in[14];
    const float* bfc  = (const float*)d_in[15];

    float* out = (float*)d_out;
    float* org = out;                              // output #1 (origin), also GRU input
    float* xs  = out + (size_t)Bc * Sc * Fc;       // output #2 (decoded, time-flipped)

    embed_kernel<<<(Bc * Sc + 127) / 128, 128>>>(x, oh, e0, e1, e2, e3, org);
    gru_kernel<<<Bc / 2, 64>>>(org, Wih1, Whh1, bih1, bhh1,
                               Wih2, Whh2, bih2, bhh2, Wfc, bfc, xs);
}